// round 6
// baseline (speedup 1.0000x reference)
#include <cuda_runtime.h>
#include <cuda_bf16.h>
#include <cstdint>

#define DINLINE __device__ __forceinline__

// ---------------- scratch (device globals; no runtime allocation) ----------
__device__ float g_partial[256];
__device__ float g_scales[4096];                        // alpha*gamma/127 per token
__device__ float g_alpha_out;                           // written by k_quant_w block 0
__device__ __align__(128) unsigned char g_wq[16777216]; // ternary W as s8, [N,K]
__device__ __align__(128) unsigned char g_xq[16777216]; // quantized x as s8, [M,K]

// ---------------- PTX helpers (baseline ISA only) ---------------------------
DINLINE uint32_t smem_u32(const void* p) {
    uint32_t a;
    asm("{ .reg .u64 t; cvta.to.shared.u64 t, %1; cvt.u32.u64 %0, t; }"
        : "=r"(a) : "l"(p));
    return a;
}
DINLINE void cp16(uint32_t dst, const void* src) {
    asm volatile("cp.async.cg.shared.global [%0], [%1], 16;" :: "r"(dst), "l"(src));
}
DINLINE void cp_commit() { asm volatile("cp.async.commit_group;" ::: "memory"); }
DINLINE void cp_wait2()  { asm volatile("cp.async.wait_group 2;" ::: "memory"); }

DINLINE void ldsm_x4(uint32_t& r0, uint32_t& r1, uint32_t& r2, uint32_t& r3, uint32_t addr) {
    asm volatile("ldmatrix.sync.aligned.m8n8.x4.shared.b16 {%0,%1,%2,%3}, [%4];"
                 : "=r"(r0), "=r"(r1), "=r"(r2), "=r"(r3) : "r"(addr));
}
DINLINE void mma_s8(int* c, uint32_t a0, uint32_t a1, uint32_t a2, uint32_t a3,
                    uint32_t b0, uint32_t b1) {
    asm volatile(
        "mma.sync.aligned.m16n8k32.row.col.s32.s8.s8.s32 "
        "{%0,%1,%2,%3}, {%4,%5,%6,%7}, {%8,%9}, {%0,%1,%2,%3};"
        : "+r"(c[0]), "+r"(c[1]), "+r"(c[2]), "+r"(c[3])
        : "r"(a0), "r"(a1), "r"(a2), "r"(a3), "r"(b0), "r"(b1));
}
DINLINE int clampi(int v, int lo, int hi) { return v < lo ? lo : (v > hi ? hi : v); }
DINLINE uint32_t pack4(int q0, int q1, int q2, int q3) {
    return (uint32_t)(q0 & 0xFF) | ((uint32_t)(q1 & 0xFF) << 8) |
           ((uint32_t)(q2 & 0xFF) << 16) | ((uint32_t)(q3 & 0xFF) << 24);
}

// ---------------- kernel 1: |W| partial sums (256 blocks, deterministic) ----
__global__ void __launch_bounds__(256) k_abs_partial(const float4* __restrict__ w) {
    __shared__ float red[256];
    const int b = blockIdx.x, t = threadIdx.x;
    const float4* p = w + (size_t)b * 16384;      // 16384 float4 per block
    float s = 0.f;
#pragma unroll 8
    for (int i = 0; i < 64; i++) {
        float4 v = p[t + 256 * i];
        s += fabsf(v.x) + fabsf(v.y) + fabsf(v.z) + fabsf(v.w);
    }
    red[t] = s; __syncthreads();
#pragma unroll
    for (int o = 128; o > 0; o >>= 1) { if (t < o) red[t] += red[t + o]; __syncthreads(); }
    if (t == 0) g_partial[b] = red[0];
}

// ---------------- kernel 2: finalize alpha (per-block) + ternary quantize W -
__global__ void __launch_bounds__(256) k_quant_w(const float4* __restrict__ w) {
    __shared__ float red[256];
    const int t = threadIdx.x;
    red[t] = g_partial[t]; __syncthreads();
#pragma unroll
    for (int o = 128; o > 0; o >>= 1) { if (t < o) red[t] += red[t + o]; __syncthreads(); }
    const float alpha = fmaxf(red[0] * (1.0f / 16777216.0f), 1e-10f);
    if (blockIdx.x == 0 && t == 0) g_alpha_out = alpha;
    const float inv_alpha = 1.0f / alpha;

    const int idx = blockIdx.x * 256 + t;          // float4 index, 4194304 total
    float4 v = w[idx];
    int q0 = clampi(__float2int_rn(v.x * inv_alpha), -1, 1);
    int q1 = clampi(__float2int_rn(v.y * inv_alpha), -1, 1);
    int q2 = clampi(__float2int_rn(v.z * inv_alpha), -1, 1);
    int q3 = clampi(__float2int_rn(v.w * inv_alpha), -1, 1);
    reinterpret_cast<uint32_t*>(g_wq)[idx] = pack4(q0, q1, q2, q3);
}

// ---------------- kernel 3: RMSNorm + per-token int8 quantize (reg-resident)
__global__ void __launch_bounds__(256) k_quant_x(const float* __restrict__ x,
                                                 const float* __restrict__ nw) {
    __shared__ float red[256];
    const int m = blockIdx.x, t = threadIdx.x;
    const float4* xr = reinterpret_cast<const float4*>(x + (size_t)m * 4096);
    const float4* nwr = reinterpret_cast<const float4*>(nw);

    float4 v[4], g[4];
    float ss = 0.f;
#pragma unroll
    for (int i = 0; i < 4; i++) {
        v[i] = xr[t + 256 * i];
        g[i] = nwr[t + 256 * i];
        ss += v[i].x * v[i].x + v[i].y * v[i].y + v[i].z * v[i].z + v[i].w * v[i].w;
    }
    red[t] = ss; __syncthreads();
#pragma unroll
    for (int o = 128; o > 0; o >>= 1) { if (t < o) red[t] += red[t + o]; __syncthreads(); }
    const float rinv = 1.0f / sqrtf(red[0] * (1.0f / 4096.0f) + 1e-6f);
    __syncthreads();

    float mx = 0.f;
#pragma unroll
    for (int i = 0; i < 4; i++) {
        v[i].x *= rinv * g[i].x; v[i].y *= rinv * g[i].y;
        v[i].z *= rinv * g[i].z; v[i].w *= rinv * g[i].w;
        mx = fmaxf(mx, fmaxf(fmaxf(fabsf(v[i].x), fabsf(v[i].y)),
                             fmaxf(fabsf(v[i].z), fabsf(v[i].w))));
    }
    red[t] = mx; __syncthreads();
#pragma unroll
    for (int o = 128; o > 0; o >>= 1) { if (t < o) red[t] = fmaxf(red[t], red[t + o]); __syncthreads(); }
    const float gamma = fmaxf(red[0], 1e-10f);
    if (t == 0) g_scales[m] = g_alpha_out * gamma * (1.0f / 127.0f);
    const float qs = 127.0f / gamma;
    uint32_t* dst = reinterpret_cast<uint32_t*>(g_xq) + (size_t)m * 1024;
#pragma unroll
    for (int i = 0; i < 4; i++) {
        int q0 = clampi(__float2int_rn(v[i].x * qs), -128, 127);
        int q1 = clampi(__float2int_rn(v[i].y * qs), -128, 127);
        int q2 = clampi(__float2int_rn(v[i].z * qs), -128, 127);
        int q3 = clampi(__float2int_rn(v[i].w * qs), -128, 127);
        dst[t + 256 * i] = pack4(q0, q1, q2, q3);
    }
}

// ---------------- kernel 4: int8 IMMA GEMM + per-row rescale ----------------
// D[m, n] = sum_k xq[m,k] * wq[n,k]  (exact in s32), y = D * scale[m]
// CTA tile 128x128, BK=64, 4-stage cp.async pipeline, 8 warps of 64x32.
// Fragments for both k32 sub-chunks are loaded up-front (12x ldmatrix.x4),
// cp.async for stage k+3 issues in the ldsm shadow, then 32 back-to-back MMAs.
static constexpr int BM = 128, BN = 128, BK = 64;
static constexpr int LDS_PAD = 80;                 // padded row stride, bank-safe
static constexpr int ASIZE = BM * LDS_PAD;         // 10240 bytes
static constexpr int STAGE = 2 * ASIZE;            // A + B = 20480 bytes
static constexpr int GEMM_SMEM = 4 * STAGE;        // 81920 bytes

__global__ void __launch_bounds__(256, 2) k_gemm(float* __restrict__ out) {
    extern __shared__ char smemraw[];
    const uint32_t sbase = smem_u32(smemraw);
    const int t = threadIdx.x;
    const int lane = t & 31, wid = t >> 5;
    const int warpM = wid >> 2;        // 0..1  -> 64-row slab
    const int warpN = wid & 3;         // 0..3  -> 32-col slab
    const int m0 = blockIdx.y * BM, n0 = blockIdx.x * BN;

    const char* gA = reinterpret_cast<const char*>(g_xq) + (size_t)m0 * 4096;
    const char* gB = reinterpret_cast<const char*>(g_wq) + (size_t)n0 * 4096;

    // loader coords: each thread copies rows lr and lr+64, 16B column lc
    const int lr = t >> 2;             // 0..63
    const int lc = (t & 3) * 16;       // 0,16,32,48
    const char* pA = gA + (size_t)lr * 4096 + lc;
    const char* pB = gB + (size_t)lr * 4096 + lc;
    const uint32_t offA = (uint32_t)(lr * LDS_PAD + lc);
    const uint32_t offB = offA + ASIZE;

    // ldmatrix per-thread address components (x4 over 16 rows x 32 bytes)
    const int xrow = (lane & 7) + ((lane >> 3) & 1) * 8;
    const int xcol = (lane >> 4) * 16;
    const uint32_t baseA = (uint32_t)((warpM * 64 + xrow) * LDS_PAD + xcol);
    const uint32_t baseB = (uint32_t)(ASIZE + (warpN * 32 + xrow) * LDS_PAD + xcol);

    int acc[4][4][4];
#pragma unroll
    for (int i = 0; i < 4; i++)
#pragma unroll
        for (int j = 0; j < 4; j++)
#pragma unroll
            for (int q = 0; q < 4; q++) acc[i][j][q] = 0;

    auto load_stage = [&](int s, int k) {
        const uint32_t dst = sbase + s * STAGE;
        const char* sA = pA + (size_t)k * BK;
        const char* sB = pB + (size_t)k * BK;
        cp16(dst + offA,                sA);
        cp16(dst + offA + 64 * LDS_PAD, sA + (size_t)64 * 4096);
        cp16(dst + offB,                sB);
        cp16(dst + offB + 64 * LDS_PAD, sB + (size_t)64 * 4096);
    };

    // prologue: stages 0..2
#pragma unroll
    for (int k = 0; k < 3; k++) { load_stage(k, k); cp_commit(); }

    for (int k = 0; k < 64; k++) {
        cp_wait2();                 // stage k's group has landed
        __syncthreads();            // all warps done with stage (k-1)&3

        const uint32_t stA = sbase + (k & 3) * STAGE;

        // ---- load ALL fragments for this 64-deep chunk (12x ldmatrix.x4) ----
        uint32_t a[2][4][4];
        uint32_t b[2][4][2];
#pragma unroll
        for (int kk = 0; kk < 2; kk++) {
#pragma unroll
            for (int i = 0; i < 4; i++)
                ldsm_x4(a[kk][i][0], a[kk][i][1], a[kk][i][2], a[kk][i][3],
                        stA + baseA + i * (16 * LDS_PAD) + kk * 32);
#pragma unroll
            for (int j2 = 0; j2 < 2; j2++) {
                uint32_t q0, q1, q2, q3;
                ldsm_x4(q0, q1, q2, q3,
                        stA + baseB + j2 * (16 * LDS_PAD) + kk * 32);
                b[kk][2 * j2][0] = q0; b[kk][2 * j2 + 1][0] = q1;
                b[kk][2 * j2][1] = q2; b[kk][2 * j2 + 1][1] = q3;
            }
        }

        // ---- issue next stage's gmem loads inside the ldsm latency shadow ----
        const int kn = k + 3;
        if (kn < 64) load_stage(kn & 3, kn);
        cp_commit();                // uniform group count (empty group at tail)

        // ---- 32 back-to-back MMAs -------------------------------------------
#pragma unroll
        for (int kk = 0; kk < 2; kk++)
#pragma unroll
            for (int i = 0; i < 4; i++)
#pragma unroll
                for (int j = 0; j < 4; j++)
                    mma_s8(acc[i][j], a[kk][i][0], a[kk][i][1], a[kk][i][2], a[kk][i][3],
                           b[kk][j][0], b[kk][j][1]);
    }

    // epilogue: scale by per-row alpha*gamma/127 and store fp32
    const int rq = lane >> 2;
    const int cq = (lane & 3) * 2;
    const int nw = n0 + warpN * 32 + cq;
#pragma unroll
    for (int i = 0; i < 4; i++) {
        const int row = m0 + warpM * 64 + i * 16 + rq;
        const float s0 = g_scales[row];
        const float s1 = g_scales[row + 8];
        float* o0 = out + (size_t)row * 4096 + nw;
        float* o1 = o0 + (size_t)8 * 4096;
#pragma unroll
        for (int j = 0; j < 4; j++) {
            float2 v0; v0.x = (float)acc[i][j][0] * s0; v0.y = (float)acc[i][j][1] * s0;
            *reinterpret_cast<float2*>(o0 + j * 8) = v0;
            float2 v1; v1.x = (float)acc[i][j][2] * s1; v1.y = (float)acc[i][j][3] * s1;
            *reinterpret_cast<float2*>(o1 + j * 8) = v1;
        }
    }
}

// ---------------- launch -----------------------------------------------------
extern "C" void kernel_launch(void* const* d_in, const int* in_sizes, int n_in,
                              void* d_out, int out_size) {
    (void)in_sizes; (void)n_in; (void)out_size;
    const float* x  = reinterpret_cast<const float*>(d_in[0]);   // [2,2048,4096]
    const float* w  = reinterpret_cast<const float*>(d_in[1]);   // [4096,4096]
    const float* nw = reinterpret_cast<const float*>(d_in[2]);   // [4096]
    float* y = reinterpret_cast<float*>(d_out);                  // [2,2048,4096]

    static bool attr_set = false;
    if (!attr_set) {
        cudaFuncSetAttribute(k_gemm, cudaFuncAttributeMaxDynamicSharedMemorySize, GEMM_SMEM);
        attr_set = true;
    }

    k_abs_partial<<<256, 256>>>(reinterpret_cast<const float4*>(w));
    k_quant_w<<<16384, 256>>>(reinterpret_cast<const float4*>(w));
    k_quant_x<<<4096, 256>>>(x, nw);
    k_gemm<<<dim3(32, 32), 256, GEMM_SMEM>>>(y);
}

// round 7
// speedup vs baseline: 1.6760x; 1.6760x over previous
#include <cuda_runtime.h>
#include <cuda_bf16.h>
#include <cstdint>

#define DINLINE __device__ __forceinline__

// ---------------- scratch (device globals; no runtime allocation) ----------
__device__ float g_partial[256];
__device__ float g_scales[4096];
__device__ float g_alpha_out;
__device__ __align__(128) unsigned char g_wq[16777216];   // W ternary s8 [N,K]
__device__ __align__(128) unsigned char g_xq[16777216];   // x quant  s8 [M,K]
__device__ __align__(128) __nv_bfloat16 g_wqh[16777216];  // W ternary bf16 [N,K]
__device__ __align__(128) __nv_bfloat16 g_xqh[16777216];  // x quant  bf16 [M,K]

// ---------------- PTX helpers (baseline ISA only) ---------------------------
DINLINE uint32_t smem_u32(const void* p) {
    uint32_t a;
    asm("{ .reg .u64 t; cvta.to.shared.u64 t, %1; cvt.u32.u64 %0, t; }"
        : "=r"(a) : "l"(p));
    return a;
}
DINLINE void cp16(uint32_t dst, const void* src) {
    asm volatile("cp.async.cg.shared.global [%0], [%1], 16;" :: "r"(dst), "l"(src));
}
DINLINE void cp_commit() { asm volatile("cp.async.commit_group;" ::: "memory"); }
DINLINE void cp_wait2()  { asm volatile("cp.async.wait_group 2;" ::: "memory"); }
DINLINE void cp_wait1()  { asm volatile("cp.async.wait_group 1;" ::: "memory"); }

DINLINE void ldsm_x4(uint32_t& r0, uint32_t& r1, uint32_t& r2, uint32_t& r3, uint32_t addr) {
    asm volatile("ldmatrix.sync.aligned.m8n8.x4.shared.b16 {%0,%1,%2,%3}, [%4];"
                 : "=r"(r0), "=r"(r1), "=r"(r2), "=r"(r3) : "r"(addr));
}
DINLINE void mma_s8(int* c, uint32_t a0, uint32_t a1, uint32_t a2, uint32_t a3,
                    uint32_t b0, uint32_t b1) {
    asm volatile(
        "mma.sync.aligned.m16n8k32.row.col.s32.s8.s8.s32 "
        "{%0,%1,%2,%3}, {%4,%5,%6,%7}, {%8,%9}, {%0,%1,%2,%3};"
        : "+r"(c[0]), "+r"(c[1]), "+r"(c[2]), "+r"(c[3])
        : "r"(a0), "r"(a1), "r"(a2), "r"(a3), "r"(b0), "r"(b1));
}
DINLINE void mma_bf16(float* c, uint32_t a0, uint32_t a1, uint32_t a2, uint32_t a3,
                      uint32_t b0, uint32_t b1) {
    asm volatile(
        "mma.sync.aligned.m16n8k16.row.col.f32.bf16.bf16.f32 "
        "{%0,%1,%2,%3}, {%4,%5,%6,%7}, {%8,%9}, {%0,%1,%2,%3};"
        : "+f"(c[0]), "+f"(c[1]), "+f"(c[2]), "+f"(c[3])
        : "r"(a0), "r"(a1), "r"(a2), "r"(a3), "r"(b0), "r"(b1));
}
DINLINE int clampi(int v, int lo, int hi) { return v < lo ? lo : (v > hi ? hi : v); }
DINLINE uint32_t pack4(int q0, int q1, int q2, int q3) {
    return (uint32_t)(q0 & 0xFF) | ((uint32_t)(q1 & 0xFF) << 8) |
           ((uint32_t)(q2 & 0xFF) << 16) | ((uint32_t)(q3 & 0xFF) << 24);
}
DINLINE uint32_t pack_bf16(float a, float b) {
    __nv_bfloat162 h;
    h.x = __float2bfloat16(a);
    h.y = __float2bfloat16(b);
    return *reinterpret_cast<uint32_t*>(&h);
}

// ---------------- kernel 1: |W| partial sums ---------------------------------
__global__ void __launch_bounds__(256) k_abs_partial(const float4* __restrict__ w) {
    __shared__ float red[256];
    const int b = blockIdx.x, t = threadIdx.x;
    const float4* p = w + (size_t)b * 16384;
    float s = 0.f;
#pragma unroll 8
    for (int i = 0; i < 64; i++) {
        float4 v = p[t + 256 * i];
        s += fabsf(v.x) + fabsf(v.y) + fabsf(v.z) + fabsf(v.w);
    }
    red[t] = s; __syncthreads();
#pragma unroll
    for (int o = 128; o > 0; o >>= 1) { if (t < o) red[t] += red[t + o]; __syncthreads(); }
    if (t == 0) g_partial[b] = red[0];
}

// ---------------- kernel 2: finalize alpha + ternary quantize W (s8 + bf16) -
__global__ void __launch_bounds__(256) k_quant_w(const float4* __restrict__ w) {
    __shared__ float red[256];
    const int t = threadIdx.x;
    red[t] = g_partial[t]; __syncthreads();
#pragma unroll
    for (int o = 128; o > 0; o >>= 1) { if (t < o) red[t] += red[t + o]; __syncthreads(); }
    const float alpha = fmaxf(red[0] * (1.0f / 16777216.0f), 1e-10f);
    if (blockIdx.x == 0 && t == 0) g_alpha_out = alpha;
    const float inv_alpha = 1.0f / alpha;

    const int idx = blockIdx.x * 256 + t;          // float4 index, 4194304 total
    float4 v = w[idx];
    int q0 = clampi(__float2int_rn(v.x * inv_alpha), -1, 1);
    int q1 = clampi(__float2int_rn(v.y * inv_alpha), -1, 1);
    int q2 = clampi(__float2int_rn(v.z * inv_alpha), -1, 1);
    int q3 = clampi(__float2int_rn(v.w * inv_alpha), -1, 1);
    reinterpret_cast<uint32_t*>(g_wq)[idx] = pack4(q0, q1, q2, q3);
    uint2 h;
    h.x = pack_bf16((float)q0, (float)q1);
    h.y = pack_bf16((float)q2, (float)q3);
    reinterpret_cast<uint2*>(g_wqh)[idx] = h;
}

// ---------------- kernel 3: RMSNorm + int8 quantize x (s8 + bf16) -----------
__global__ void __launch_bounds__(256) k_quant_x(const float* __restrict__ x,
                                                 const float* __restrict__ nw) {
    __shared__ float red[256];
    const int m = blockIdx.x, t = threadIdx.x;
    const float4* xr = reinterpret_cast<const float4*>(x + (size_t)m * 4096);
    const float4* nwr = reinterpret_cast<const float4*>(nw);

    float4 v[4], g[4];
    float ss = 0.f;
#pragma unroll
    for (int i = 0; i < 4; i++) {
        v[i] = xr[t + 256 * i];
        g[i] = nwr[t + 256 * i];
        ss += v[i].x * v[i].x + v[i].y * v[i].y + v[i].z * v[i].z + v[i].w * v[i].w;
    }
    red[t] = ss; __syncthreads();
#pragma unroll
    for (int o = 128; o > 0; o >>= 1) { if (t < o) red[t] += red[t + o]; __syncthreads(); }
    const float rinv = 1.0f / sqrtf(red[0] * (1.0f / 4096.0f) + 1e-6f);
    __syncthreads();

    float mx = 0.f;
#pragma unroll
    for (int i = 0; i < 4; i++) {
        v[i].x *= rinv * g[i].x; v[i].y *= rinv * g[i].y;
        v[i].z *= rinv * g[i].z; v[i].w *= rinv * g[i].w;
        mx = fmaxf(mx, fmaxf(fmaxf(fabsf(v[i].x), fabsf(v[i].y)),
                             fmaxf(fabsf(v[i].z), fabsf(v[i].w))));
    }
    red[t] = mx; __syncthreads();
#pragma unroll
    for (int o = 128; o > 0; o >>= 1) { if (t < o) red[t] = fmaxf(red[t], red[t + o]); __syncthreads(); }
    const float gamma = fmaxf(red[0], 1e-10f);
    if (t == 0) g_scales[m] = g_alpha_out * gamma * (1.0f / 127.0f);
    const float qs = 127.0f / gamma;
    uint32_t* dst  = reinterpret_cast<uint32_t*>(g_xq) + (size_t)m * 1024;
    uint2*    dsth = reinterpret_cast<uint2*>(g_xqh)   + (size_t)m * 1024;
#pragma unroll
    for (int i = 0; i < 4; i++) {
        int q0 = clampi(__float2int_rn(v[i].x * qs), -128, 127);
        int q1 = clampi(__float2int_rn(v[i].y * qs), -128, 127);
        int q2 = clampi(__float2int_rn(v[i].z * qs), -128, 127);
        int q3 = clampi(__float2int_rn(v[i].w * qs), -128, 127);
        dst[t + 256 * i] = pack4(q0, q1, q2, q3);
        uint2 h;
        h.x = pack_bf16((float)q0, (float)q1);
        h.y = pack_bf16((float)q2, (float)q3);
        dsth[t + 256 * i] = h;
    }
}

// ================= GEMM A: s8 IMMA (rows [0,2048)) — R5-proven structure ====
static constexpr int LDS_PAD8 = 80;
static constexpr int ASIZE8 = 128 * LDS_PAD8;       // 10240
static constexpr int STAGE8 = 2 * ASIZE8;           // 20480
static constexpr int SMEM8  = 4 * STAGE8;           // 81920

__global__ void __launch_bounds__(256, 2) k_gemm_s8(float* __restrict__ out) {
    extern __shared__ char smemraw[];
    const uint32_t sbase = smem_u32(smemraw);
    const int t = threadIdx.x;
    const int lane = t & 31, wid = t >> 5;
    const int warpM = wid >> 2, warpN = wid & 3;
    const int m0 = blockIdx.y * 128, n0 = blockIdx.x * 128;

    const char* gA = reinterpret_cast<const char*>(g_xq) + (size_t)m0 * 4096;
    const char* gB = reinterpret_cast<const char*>(g_wq) + (size_t)n0 * 4096;

    const int lr = t >> 2;
    const int lc = (t & 3) * 16;
    const char* pA = gA + (size_t)lr * 4096 + lc;
    const char* pB = gB + (size_t)lr * 4096 + lc;
    const uint32_t offA = (uint32_t)(lr * LDS_PAD8 + lc);
    const uint32_t offB = offA + ASIZE8;

    const int xrow = (lane & 7) + ((lane >> 3) & 1) * 8;
    const int xcol = (lane >> 4) * 16;
    const uint32_t baseA = (uint32_t)((warpM * 64 + xrow) * LDS_PAD8 + xcol);
    const uint32_t baseB = (uint32_t)(ASIZE8 + (warpN * 32 + xrow) * LDS_PAD8 + xcol);

    int acc[4][4][4];
#pragma unroll
    for (int i = 0; i < 4; i++)
#pragma unroll
        for (int j = 0; j < 4; j++)
#pragma unroll
            for (int q = 0; q < 4; q++) acc[i][j][q] = 0;

    auto load_stage = [&](int s, int k) {
        const uint32_t dst = sbase + s * STAGE8;
        const char* sA = pA + (size_t)k * 64;
        const char* sB = pB + (size_t)k * 64;
        cp16(dst + offA,                 sA);
        cp16(dst + offA + 64 * LDS_PAD8, sA + (size_t)64 * 4096);
        cp16(dst + offB,                 sB);
        cp16(dst + offB + 64 * LDS_PAD8, sB + (size_t)64 * 4096);
    };

#pragma unroll
    for (int k = 0; k < 3; k++) { load_stage(k, k); cp_commit(); }

    for (int k = 0; k < 64; k++) {
        cp_wait2();
        __syncthreads();

        const int kn = k + 3;
        if (kn < 64) load_stage(kn & 3, kn);
        cp_commit();

        const uint32_t stA = sbase + (k & 3) * STAGE8;
#pragma unroll
        for (int kk = 0; kk < 2; kk++) {
            uint32_t a[4][4];
#pragma unroll
            for (int i = 0; i < 4; i++)
                ldsm_x4(a[i][0], a[i][1], a[i][2], a[i][3],
                        stA + baseA + i * (16 * LDS_PAD8) + kk * 32);
            uint32_t b[4][2];
#pragma unroll
            for (int j2 = 0; j2 < 2; j2++) {
                uint32_t q0, q1, q2, q3;
                ldsm_x4(q0, q1, q2, q3,
                        stA + baseB + j2 * (16 * LDS_PAD8) + kk * 32);
                b[2 * j2][0] = q0; b[2 * j2 + 1][0] = q1;
                b[2 * j2][1] = q2; b[2 * j2 + 1][1] = q3;
            }
#pragma unroll
            for (int i = 0; i < 4; i++)
#pragma unroll
                for (int j = 0; j < 4; j++)
                    mma_s8(acc[i][j], a[i][0], a[i][1], a[i][2], a[i][3], b[j][0], b[j][1]);
        }
    }

    const int rq = lane >> 2;
    const int cq = (lane & 3) * 2;
    const int nw = n0 + warpN * 32 + cq;
#pragma unroll
    for (int i = 0; i < 4; i++) {
        const int row = m0 + warpM * 64 + i * 16 + rq;
        const float s0 = g_scales[row];
        const float s1 = g_scales[row + 8];
        float* o0 = out + (size_t)row * 4096 + nw;
        float* o1 = o0 + (size_t)8 * 4096;
#pragma unroll
        for (int j = 0; j < 4; j++) {
            float2 v0; v0.x = (float)acc[i][j][0] * s0; v0.y = (float)acc[i][j][1] * s0;
            *reinterpret_cast<float2*>(o0 + j * 8) = v0;
            float2 v1; v1.x = (float)acc[i][j][2] * s1; v1.y = (float)acc[i][j][3] * s1;
            *reinterpret_cast<float2*>(o1 + j * 8) = v1;
        }
    }
}

// ================= GEMM B: bf16 HMMA (rows [2048,4096)) =====================
// BK = 64 bf16 elems = 128B rows; pad stride 144 (conflict-free ldsm);
// 3-stage cp.async pipeline (110.6KB smem, occ 2).
static constexpr int LDS_PADH = 144;
static constexpr int ASIZEH = 128 * LDS_PADH;       // 18432
static constexpr int STAGEH = 2 * ASIZEH;           // 36864
static constexpr int SMEMH  = 3 * STAGEH;           // 110592

__global__ void __launch_bounds__(256, 2) k_gemm_bf16(float* __restrict__ out) {
    extern __shared__ char smemraw[];
    const uint32_t sbase = smem_u32(smemraw);
    const int t = threadIdx.x;
    const int lane = t & 31, wid = t >> 5;
    const int warpM = wid >> 2, warpN = wid & 3;
    const int m0 = 2048 + blockIdx.y * 128, n0 = blockIdx.x * 128;

    const char* gA = reinterpret_cast<const char*>(g_xqh) + (size_t)m0 * 8192;
    const char* gB = reinterpret_cast<const char*>(g_wqh) + (size_t)n0 * 8192;

    // loader: 2 threads per 128B chunk-row; each does 4 cp16
    const int lr = t >> 1;              // 0..127
    const int lc = (t & 1) * 64;        // 0 or 64
    const char* pA = gA + (size_t)lr * 8192 + lc;
    const char* pB = gB + (size_t)lr * 8192 + lc;
    const uint32_t offA = (uint32_t)(lr * LDS_PADH + lc);
    const uint32_t offB = offA + ASIZEH;

    const int xrow = (lane & 7) + ((lane >> 3) & 1) * 8;
    const int xcol = (lane >> 4) * 16;
    const uint32_t baseA = (uint32_t)((warpM * 64 + xrow) * LDS_PADH + xcol);
    const uint32_t baseB = (uint32_t)(ASIZEH + (warpN * 32 + xrow) * LDS_PADH + xcol);

    float acc[4][4][4];
#pragma unroll
    for (int i = 0; i < 4; i++)
#pragma unroll
        for (int j = 0; j < 4; j++)
#pragma unroll
            for (int q = 0; q < 4; q++) acc[i][j][q] = 0.f;

    auto load_stage = [&](int s, int k) {
        const uint32_t dst = sbase + s * STAGEH;
        const char* sA = pA + (size_t)k * 128;
        const char* sB = pB + (size_t)k * 128;
#pragma unroll
        for (int i = 0; i < 4; i++) {
            cp16(dst + offA + i * 16, sA + i * 16);
            cp16(dst + offB + i * 16, sB + i * 16);
        }
    };

#pragma unroll
    for (int k = 0; k < 2; k++) { load_stage(k, k); cp_commit(); }

    for (int k = 0; k < 64; k++) {
        cp_wait1();
        __syncthreads();

        const int kn = k + 2;
        if (kn < 64) {
            int sn = kn % 3;
            load_stage(sn, kn);
        }
        cp_commit();

        const uint32_t stA = sbase + (k % 3) * STAGEH;
#pragma unroll
        for (int kk = 0; kk < 4; kk++) {   // 4 k16 sub-chunks (32B each)
            uint32_t a[4][4];
#pragma unroll
            for (int i = 0; i < 4; i++)
                ldsm_x4(a[i][0], a[i][1], a[i][2], a[i][3],
                        stA + baseA + i * (16 * LDS_PADH) + kk * 32);
            uint32_t b[4][2];
#pragma unroll
            for (int j2 = 0; j2 < 2; j2++) {
                uint32_t q0, q1, q2, q3;
                ldsm_x4(q0, q1, q2, q3,
                        stA + baseB + j2 * (16 * LDS_PADH) + kk * 32);
                b[2 * j2][0] = q0; b[2 * j2 + 1][0] = q1;
                b[2 * j2][1] = q2; b[2 * j2 + 1][1] = q3;
            }
#pragma unroll
            for (int i = 0; i < 4; i++)
#pragma unroll
                for (int j = 0; j < 4; j++)
                    mma_bf16(acc[i][j], a[i][0], a[i][1], a[i][2], a[i][3],
                             b[j][0], b[j][1]);
        }
    }

    const int rq = lane >> 2;
    const int cq = (lane & 3) * 2;
    const int nw = n0 + warpN * 32 + cq;
#pragma unroll
    for (int i = 0; i < 4; i++) {
        const int row = m0 + warpM * 64 + i * 16 + rq;
        const float s0 = g_scales[row];
        const float s1 = g_scales[row + 8];
        float* o0 = out + (size_t)row * 4096 + nw;
        float* o1 = o0 + (size_t)8 * 4096;
#pragma unroll
        for (int j = 0; j < 4; j++) {
            float2 v0; v0.x = acc[i][j][0] * s0; v0.y = acc[i][j][1] * s0;
            *reinterpret_cast<float2*>(o0 + j * 8) = v0;
            float2 v1; v1.x = acc[i][j][2] * s1; v1.y = acc[i][j][3] * s1;
            *reinterpret_cast<float2*>(o1 + j * 8) = v1;
        }
    }
}

// ---------------- launch -----------------------------------------------------
extern "C" void kernel_launch(void* const* d_in, const int* in_sizes, int n_in,
                              void* d_out, int out_size) {
    (void)in_sizes; (void)n_in; (void)out_size;
    const float* x  = reinterpret_cast<const float*>(d_in[0]);
    const float* w  = reinterpret_cast<const float*>(d_in[1]);
    const float* nw = reinterpret_cast<const float*>(d_in[2]);
    float* y = reinterpret_cast<float*>(d_out);

    static bool attr_set = false;
    if (!attr_set) {
        cudaFuncSetAttribute(k_gemm_s8,   cudaFuncAttributeMaxDynamicSharedMemorySize, SMEM8);
        cudaFuncSetAttribute(k_gemm_bf16, cudaFuncAttributeMaxDynamicSharedMemorySize, SMEMH);
        attr_set = true;
    }

    k_abs_partial<<<256, 256>>>(reinterpret_cast<const float4*>(w));
    k_quant_w<<<16384, 256>>>(reinterpret_cast<const float4*>(w));
    k_quant_x<<<4096, 256>>>(x, nw);
    k_gemm_s8<<<dim3(32, 16), 256, SMEM8>>>(y);     // rows [0, 2048)
    k_gemm_bf16<<<dim3(32, 16), 256, SMEMH>>>(y);   // rows [2048, 4096)
}

// round 8
// speedup vs baseline: 2.4213x; 1.4447x over previous
#include <cuda_runtime.h>
#include <cuda_bf16.h>
#include <cstdint>

#define DINLINE __device__ __forceinline__

// ---------------- scratch (device globals; no runtime allocation) ----------
__device__ float g_partial[256];
__device__ float g_scales[4096];
__device__ float g_alpha_out;
__device__ __align__(128) __nv_bfloat16 g_wqh[16777216];  // W ternary bf16 [N,K]
__device__ __align__(128) __nv_bfloat16 g_xqh[16777216];  // x quant  bf16 [M,K]

// ---------------- PTX helpers (baseline ISA only) ---------------------------
DINLINE uint32_t smem_u32(const void* p) {
    uint32_t a;
    asm("{ .reg .u64 t; cvta.to.shared.u64 t, %1; cvt.u32.u64 %0, t; }"
        : "=r"(a) : "l"(p));
    return a;
}
DINLINE void cp16(uint32_t dst, const void* src) {
    asm volatile("cp.async.cg.shared.global [%0], [%1], 16;" :: "r"(dst), "l"(src));
}
DINLINE void cp_commit() { asm volatile("cp.async.commit_group;" ::: "memory"); }
DINLINE void cp_wait1()  { asm volatile("cp.async.wait_group 1;" ::: "memory"); }

DINLINE void ldsm_x4(uint32_t& r0, uint32_t& r1, uint32_t& r2, uint32_t& r3, uint32_t addr) {
    asm volatile("ldmatrix.sync.aligned.m8n8.x4.shared.b16 {%0,%1,%2,%3}, [%4];"
                 : "=r"(r0), "=r"(r1), "=r"(r2), "=r"(r3) : "r"(addr));
}
DINLINE void mma_bf16(float* c, uint32_t a0, uint32_t a1, uint32_t a2, uint32_t a3,
                      uint32_t b0, uint32_t b1) {
    asm volatile(
        "mma.sync.aligned.m16n8k16.row.col.f32.bf16.bf16.f32 "
        "{%0,%1,%2,%3}, {%4,%5,%6,%7}, {%8,%9}, {%0,%1,%2,%3};"
        : "+f"(c[0]), "+f"(c[1]), "+f"(c[2]), "+f"(c[3])
        : "r"(a0), "r"(a1), "r"(a2), "r"(a3), "r"(b0), "r"(b1));
}
DINLINE int clampi(int v, int lo, int hi) { return v < lo ? lo : (v > hi ? hi : v); }
DINLINE uint32_t pack_bf16(float a, float b) {
    __nv_bfloat162 h;
    h.x = __float2bfloat16(a);
    h.y = __float2bfloat16(b);
    return *reinterpret_cast<uint32_t*>(&h);
}

// ---------------- kernel 1: |W| partial sums ---------------------------------
__global__ void __launch_bounds__(256) k_abs_partial(const float4* __restrict__ w) {
    __shared__ float red[256];
    const int b = blockIdx.x, t = threadIdx.x;
    const float4* p = w + (size_t)b * 16384;
    float s = 0.f;
#pragma unroll 8
    for (int i = 0; i < 64; i++) {
        float4 v = p[t + 256 * i];
        s += fabsf(v.x) + fabsf(v.y) + fabsf(v.z) + fabsf(v.w);
    }
    red[t] = s; __syncthreads();
#pragma unroll
    for (int o = 128; o > 0; o >>= 1) { if (t < o) red[t] += red[t + o]; __syncthreads(); }
    if (t == 0) g_partial[b] = red[0];
}

// ---------------- kernel 2: finalize alpha + ternary quantize W -> bf16 -----
__global__ void __launch_bounds__(256) k_quant_w(const float4* __restrict__ w) {
    __shared__ float red[256];
    const int t = threadIdx.x;
    red[t] = g_partial[t]; __syncthreads();
#pragma unroll
    for (int o = 128; o > 0; o >>= 1) { if (t < o) red[t] += red[t + o]; __syncthreads(); }
    const float alpha = fmaxf(red[0] * (1.0f / 16777216.0f), 1e-10f);
    if (blockIdx.x == 0 && t == 0) g_alpha_out = alpha;
    const float inv_alpha = 1.0f / alpha;

    const int idx = blockIdx.x * 256 + t;          // float4 index, 4194304 total
    float4 v = w[idx];
    int q0 = clampi(__float2int_rn(v.x * inv_alpha), -1, 1);
    int q1 = clampi(__float2int_rn(v.y * inv_alpha), -1, 1);
    int q2 = clampi(__float2int_rn(v.z * inv_alpha), -1, 1);
    int q3 = clampi(__float2int_rn(v.w * inv_alpha), -1, 1);
    uint2 h;
    h.x = pack_bf16((float)q0, (float)q1);
    h.y = pack_bf16((float)q2, (float)q3);
    reinterpret_cast<uint2*>(g_wqh)[idx] = h;
}

// ---------------- kernel 3: RMSNorm + int8-grid quantize x -> bf16 ----------
__global__ void __launch_bounds__(256) k_quant_x(const float* __restrict__ x,
                                                 const float* __restrict__ nw) {
    __shared__ float red[256];
    const int m = blockIdx.x, t = threadIdx.x;
    const float4* xr = reinterpret_cast<const float4*>(x + (size_t)m * 4096);
    const float4* nwr = reinterpret_cast<const float4*>(nw);

    float4 v[4], g[4];
    float ss = 0.f;
#pragma unroll
    for (int i = 0; i < 4; i++) {
        v[i] = xr[t + 256 * i];
        g[i] = nwr[t + 256 * i];
        ss += v[i].x * v[i].x + v[i].y * v[i].y + v[i].z * v[i].z + v[i].w * v[i].w;
    }
    red[t] = ss; __syncthreads();
#pragma unroll
    for (int o = 128; o > 0; o >>= 1) { if (t < o) red[t] += red[t + o]; __syncthreads(); }
    const float rinv = 1.0f / sqrtf(red[0] * (1.0f / 4096.0f) + 1e-6f);
    __syncthreads();

    float mx = 0.f;
#pragma unroll
    for (int i = 0; i < 4; i++) {
        v[i].x *= rinv * g[i].x; v[i].y *= rinv * g[i].y;
        v[i].z *= rinv * g[i].z; v[i].w *= rinv * g[i].w;
        mx = fmaxf(mx, fmaxf(fmaxf(fabsf(v[i].x), fabsf(v[i].y)),
                             fmaxf(fabsf(v[i].z), fabsf(v[i].w))));
    }
    red[t] = mx; __syncthreads();
#pragma unroll
    for (int o = 128; o > 0; o >>= 1) { if (t < o) red[t] = fmaxf(red[t], red[t + o]); __syncthreads(); }
    const float gamma = fmaxf(red[0], 1e-10f);
    if (t == 0) g_scales[m] = g_alpha_out * gamma * (1.0f / 127.0f);
    const float qs = 127.0f / gamma;
    uint2* dsth = reinterpret_cast<uint2*>(g_xqh) + (size_t)m * 1024;
#pragma unroll
    for (int i = 0; i < 4; i++) {
        int q0 = clampi(__float2int_rn(v[i].x * qs), -128, 127);
        int q1 = clampi(__float2int_rn(v[i].y * qs), -128, 127);
        int q2 = clampi(__float2int_rn(v[i].z * qs), -128, 127);
        int q3 = clampi(__float2int_rn(v[i].w * qs), -128, 127);
        uint2 h;
        h.x = pack_bf16((float)q0, (float)q1);
        h.y = pack_bf16((float)q2, (float)q3);
        dsth[t + 256 * i] = h;
    }
}

// ================= bf16 HMMA GEMM (full M) + per-row rescale ================
// D[m,n] = sum_k xq[m,k] * wq[n,k]  (exact: integers in bf16, fp32 accum)
// CTA tile 128x128, BK=64 bf16 (128B rows), pad-144 smem (conflict-free ldsm),
// 3-stage cp.async pipeline, 8 warps of 64x32, occ 2.
static constexpr int LDS_PADH = 144;
static constexpr int ASIZEH = 128 * LDS_PADH;       // 18432
static constexpr int STAGEH = 2 * ASIZEH;           // 36864
static constexpr int SMEMH  = 3 * STAGEH;           // 110592

__global__ void __launch_bounds__(256, 2) k_gemm_bf16(float* __restrict__ out) {
    extern __shared__ char smemraw[];
    const uint32_t sbase = smem_u32(smemraw);
    const int t = threadIdx.x;
    const int lane = t & 31, wid = t >> 5;
    const int warpM = wid >> 2, warpN = wid & 3;
    const int m0 = blockIdx.y * 128, n0 = blockIdx.x * 128;

    const char* gA = reinterpret_cast<const char*>(g_xqh) + (size_t)m0 * 8192;
    const char* gB = reinterpret_cast<const char*>(g_wqh) + (size_t)n0 * 8192;

    // loader: 2 threads per 128B row chunk, 4x cp16 each for A and B
    const int lr = t >> 1;              // 0..127
    const int lc = (t & 1) * 64;        // 0 or 64
    const char* pA = gA + (size_t)lr * 8192 + lc;
    const char* pB = gB + (size_t)lr * 8192 + lc;
    const uint32_t offA = (uint32_t)(lr * LDS_PADH + lc);
    const uint32_t offB = offA + ASIZEH;

    const int xrow = (lane & 7) + ((lane >> 3) & 1) * 8;
    const int xcol = (lane >> 4) * 16;
    const uint32_t baseA = (uint32_t)((warpM * 64 + xrow) * LDS_PADH + xcol);
    const uint32_t baseB = (uint32_t)(ASIZEH + (warpN * 32 + xrow) * LDS_PADH + xcol);

    float acc[4][4][4];
#pragma unroll
    for (int i = 0; i < 4; i++)
#pragma unroll
        for (int j = 0; j < 4; j++)
#pragma unroll
            for (int q = 0; q < 4; q++) acc[i][j][q] = 0.f;

    auto load_stage = [&](int s, int k) {
        const uint32_t dst = sbase + s * STAGEH;
        const char* sA = pA + (size_t)k * 128;
        const char* sB = pB + (size_t)k * 128;
#pragma unroll
        for (int i = 0; i < 4; i++) {
            cp16(dst + offA + i * 16, sA + i * 16);
            cp16(dst + offB + i * 16, sB + i * 16);
        }
    };

#pragma unroll
    for (int k = 0; k < 2; k++) { load_stage(k, k); cp_commit(); }

    for (int k = 0; k < 64; k++) {
        cp_wait1();
        __syncthreads();

        const int kn = k + 2;
        if (kn < 64) load_stage(kn % 3, kn);
        cp_commit();

        const uint32_t stA = sbase + (k % 3) * STAGEH;
#pragma unroll
        for (int kk = 0; kk < 4; kk++) {   // 4 k16 sub-chunks (32B each)
            uint32_t a[4][4];
#pragma unroll
            for (int i = 0; i < 4; i++)
                ldsm_x4(a[i][0], a[i][1], a[i][2], a[i][3],
                        stA + baseA + i * (16 * LDS_PADH) + kk * 32);
            uint32_t b[4][2];
#pragma unroll
            for (int j2 = 0; j2 < 2; j2++) {
                uint32_t q0, q1, q2, q3;
                ldsm_x4(q0, q1, q2, q3,
                        stA + baseB + j2 * (16 * LDS_PADH) + kk * 32);
                b[2 * j2][0] = q0; b[2 * j2 + 1][0] = q1;
                b[2 * j2][1] = q2; b[2 * j2 + 1][1] = q3;
            }
#pragma unroll
            for (int i = 0; i < 4; i++)
#pragma unroll
                for (int j = 0; j < 4; j++)
                    mma_bf16(acc[i][j], a[i][0], a[i][1], a[i][2], a[i][3],
                             b[j][0], b[j][1]);
        }
    }

    const int rq = lane >> 2;
    const int cq = (lane & 3) * 2;
    const int nw = n0 + warpN * 32 + cq;
#pragma unroll
    for (int i = 0; i < 4; i++) {
        const int row = m0 + warpM * 64 + i * 16 + rq;
        const float s0 = g_scales[row];
        const float s1 = g_scales[row + 8];
        float* o0 = out + (size_t)row * 4096 + nw;
        float* o1 = o0 + (size_t)8 * 4096;
#pragma unroll
        for (int j = 0; j < 4; j++) {
            float2 v0; v0.x = acc[i][j][0] * s0; v0.y = acc[i][j][1] * s0;
            *reinterpret_cast<float2*>(o0 + j * 8) = v0;
            float2 v1; v1.x = acc[i][j][2] * s1; v1.y = acc[i][j][3] * s1;
            *reinterpret_cast<float2*>(o1 + j * 8) = v1;
        }
    }
}

// ---------------- launch -----------------------------------------------------
extern "C" void kernel_launch(void* const* d_in, const int* in_sizes, int n_in,
                              void* d_out, int out_size) {
    (void)in_sizes; (void)n_in; (void)out_size;
    const float* x  = reinterpret_cast<const float*>(d_in[0]);
    const float* w  = reinterpret_cast<const float*>(d_in[1]);
    const float* nw = reinterpret_cast<const float*>(d_in[2]);
    float* y = reinterpret_cast<float*>(d_out);

    static bool attr_set = false;
    if (!attr_set) {
        cudaFuncSetAttribute(k_gemm_bf16, cudaFuncAttributeMaxDynamicSharedMemorySize, SMEMH);
        attr_set = true;
    }

    k_abs_partial<<<256, 256>>>(reinterpret_cast<const float4*>(w));
    k_quant_w<<<16384, 256>>>(reinterpret_cast<const float4*>(w));
    k_quant_x<<<4096, 256>>>(x, nw);
    k_gemm_bf16<<<dim3(32, 32), 256, SMEMH>>>(y);
}

// round 9
// speedup vs baseline: 2.5572x; 1.0561x over previous
#include <cuda_runtime.h>
#include <cuda_bf16.h>
#include <cstdint>

#define DINLINE __device__ __forceinline__

// ---------------- scratch (device globals; no runtime allocation) ----------
__device__ float g_partial[256];
__device__ float g_scales[4096];
__device__ float g_alpha_out;
__device__ __align__(128) __nv_bfloat16 g_wqh[16777216];  // W ternary bf16 [N,K]
__device__ __align__(128) __nv_bfloat16 g_xqh[16777216];  // x quant  bf16 [M,K]

// ---------------- PTX helpers (baseline ISA only) ---------------------------
DINLINE uint32_t smem_u32(const void* p) {
    uint32_t a;
    asm("{ .reg .u64 t; cvta.to.shared.u64 t, %1; cvt.u32.u64 %0, t; }"
        : "=r"(a) : "l"(p));
    return a;
}
DINLINE void cp16(uint32_t dst, const void* src) {
    asm volatile("cp.async.cg.shared.global [%0], [%1], 16;" :: "r"(dst), "l"(src));
}
DINLINE void cp_commit() { asm volatile("cp.async.commit_group;" ::: "memory"); }
DINLINE void cp_wait2()  { asm volatile("cp.async.wait_group 2;" ::: "memory"); }

DINLINE void ldsm_x4(uint32_t& r0, uint32_t& r1, uint32_t& r2, uint32_t& r3, uint32_t addr) {
    asm volatile("ldmatrix.sync.aligned.m8n8.x4.shared.b16 {%0,%1,%2,%3}, [%4];"
                 : "=r"(r0), "=r"(r1), "=r"(r2), "=r"(r3) : "r"(addr));
}
DINLINE void mma_bf16(float* c, uint32_t a0, uint32_t a1, uint32_t a2, uint32_t a3,
                      uint32_t b0, uint32_t b1) {
    asm volatile(
        "mma.sync.aligned.m16n8k16.row.col.f32.bf16.bf16.f32 "
        "{%0,%1,%2,%3}, {%4,%5,%6,%7}, {%8,%9}, {%0,%1,%2,%3};"
        : "+f"(c[0]), "+f"(c[1]), "+f"(c[2]), "+f"(c[3])
        : "r"(a0), "r"(a1), "r"(a2), "r"(a3), "r"(b0), "r"(b1));
}
DINLINE int clampi(int v, int lo, int hi) { return v < lo ? lo : (v > hi ? hi : v); }
DINLINE uint32_t pack_bf16(float a, float b) {
    __nv_bfloat162 h;
    h.x = __float2bfloat16(a);
    h.y = __float2bfloat16(b);
    return *reinterpret_cast<uint32_t*>(&h);
}

// ---------------- kernel 1: |W| partial sums ---------------------------------
__global__ void __launch_bounds__(256) k_abs_partial(const float4* __restrict__ w) {
    __shared__ float red[256];
    const int b = blockIdx.x, t = threadIdx.x;
    const float4* p = w + (size_t)b * 16384;
    float s = 0.f;
#pragma unroll 8
    for (int i = 0; i < 64; i++) {
        float4 v = p[t + 256 * i];
        s += fabsf(v.x) + fabsf(v.y) + fabsf(v.z) + fabsf(v.w);
    }
    red[t] = s; __syncthreads();
#pragma unroll
    for (int o = 128; o > 0; o >>= 1) { if (t < o) red[t] += red[t + o]; __syncthreads(); }
    if (t == 0) g_partial[b] = red[0];
}

// ---------------- kernel 2: finalize alpha + ternary quantize W -> bf16 -----
__global__ void __launch_bounds__(256) k_quant_w(const float4* __restrict__ w) {
    __shared__ float red[256];
    const int t = threadIdx.x;
    red[t] = g_partial[t]; __syncthreads();
#pragma unroll
    for (int o = 128; o > 0; o >>= 1) { if (t < o) red[t] += red[t + o]; __syncthreads(); }
    const float alpha = fmaxf(red[0] * (1.0f / 16777216.0f), 1e-10f);
    if (blockIdx.x == 0 && t == 0) g_alpha_out = alpha;
    const float inv_alpha = 1.0f / alpha;

    const int idx = blockIdx.x * 256 + t;          // float4 index, 4194304 total
    float4 v = w[idx];
    int q0 = clampi(__float2int_rn(v.x * inv_alpha), -1, 1);
    int q1 = clampi(__float2int_rn(v.y * inv_alpha), -1, 1);
    int q2 = clampi(__float2int_rn(v.z * inv_alpha), -1, 1);
    int q3 = clampi(__float2int_rn(v.w * inv_alpha), -1, 1);
    uint2 h;
    h.x = pack_bf16((float)q0, (float)q1);
    h.y = pack_bf16((float)q2, (float)q3);
    reinterpret_cast<uint2*>(g_wqh)[idx] = h;
}

// ---------------- kernel 3: RMSNorm + int8-grid quantize x -> bf16 ----------
__global__ void __launch_bounds__(256) k_quant_x(const float* __restrict__ x,
                                                 const float* __restrict__ nw) {
    __shared__ float red[256];
    const int m = blockIdx.x, t = threadIdx.x;
    const float4* xr = reinterpret_cast<const float4*>(x + (size_t)m * 4096);
    const float4* nwr = reinterpret_cast<const float4*>(nw);

    float4 v[4], g[4];
    float ss = 0.f;
#pragma unroll
    for (int i = 0; i < 4; i++) {
        v[i] = xr[t + 256 * i];
        g[i] = nwr[t + 256 * i];
        ss += v[i].x * v[i].x + v[i].y * v[i].y + v[i].z * v[i].z + v[i].w * v[i].w;
    }
    red[t] = ss; __syncthreads();
#pragma unroll
    for (int o = 128; o > 0; o >>= 1) { if (t < o) red[t] += red[t + o]; __syncthreads(); }
    const float rinv = 1.0f / sqrtf(red[0] * (1.0f / 4096.0f) + 1e-6f);
    __syncthreads();

    float mx = 0.f;
#pragma unroll
    for (int i = 0; i < 4; i++) {
        v[i].x *= rinv * g[i].x; v[i].y *= rinv * g[i].y;
        v[i].z *= rinv * g[i].z; v[i].w *= rinv * g[i].w;
        mx = fmaxf(mx, fmaxf(fmaxf(fabsf(v[i].x), fabsf(v[i].y)),
                             fmaxf(fabsf(v[i].z), fabsf(v[i].w))));
    }
    red[t] = mx; __syncthreads();
#pragma unroll
    for (int o = 128; o > 0; o >>= 1) { if (t < o) red[t] = fmaxf(red[t], red[t + o]); __syncthreads(); }
    const float gamma = fmaxf(red[0], 1e-10f);
    if (t == 0) g_scales[m] = g_alpha_out * gamma * (1.0f / 127.0f);
    const float qs = 127.0f / gamma;
    uint2* dsth = reinterpret_cast<uint2*>(g_xqh) + (size_t)m * 1024;
#pragma unroll
    for (int i = 0; i < 4; i++) {
        int q0 = clampi(__float2int_rn(v[i].x * qs), -128, 127);
        int q1 = clampi(__float2int_rn(v[i].y * qs), -128, 127);
        int q2 = clampi(__float2int_rn(v[i].z * qs), -128, 127);
        int q3 = clampi(__float2int_rn(v[i].w * qs), -128, 127);
        uint2 h;
        h.x = pack_bf16((float)q0, (float)q1);
        h.y = pack_bf16((float)q2, (float)q3);
        dsth[t + 256 * i] = h;
    }
}

// ================= bf16 HMMA GEMM (full M) + per-row rescale ================
// D[m,n] = sum_k xq[m,k] * wq[n,k]  (exact: integers in bf16, fp32 accum)
// CTA tile 128x128, BK=64 bf16 (128B rows), pad-144 smem (conflict-free ldsm),
// 4-stage cp.async pipeline, 8 warps of 64x32, 1 CTA/SM,
// register-level fragment double-buffering (ldsm for kk+1 overlaps MMAs of kk).
static constexpr int LDS_PADH = 144;
static constexpr int ASIZEH = 128 * LDS_PADH;       // 18432
static constexpr int STAGEH = 2 * ASIZEH;           // 36864
static constexpr int SMEMH  = 4 * STAGEH;           // 147456

__global__ void __launch_bounds__(256, 1) k_gemm_bf16(float* __restrict__ out) {
    extern __shared__ char smemraw[];
    const uint32_t sbase = smem_u32(smemraw);
    const int t = threadIdx.x;
    const int lane = t & 31, wid = t >> 5;
    const int warpM = wid >> 2, warpN = wid & 3;
    const int m0 = blockIdx.y * 128, n0 = blockIdx.x * 128;

    const char* gA = reinterpret_cast<const char*>(g_xqh) + (size_t)m0 * 8192;
    const char* gB = reinterpret_cast<const char*>(g_wqh) + (size_t)n0 * 8192;

    // loader: 2 threads per 128B row chunk, 4x cp16 each for A and B
    const int lr = t >> 1;              // 0..127
    const int lc = (t & 1) * 64;        // 0 or 64
    const char* pA = gA + (size_t)lr * 8192 + lc;
    const char* pB = gB + (size_t)lr * 8192 + lc;
    const uint32_t offA = (uint32_t)(lr * LDS_PADH + lc);
    const uint32_t offB = offA + ASIZEH;

    const int xrow = (lane & 7) + ((lane >> 3) & 1) * 8;
    const int xcol = (lane >> 4) * 16;
    const uint32_t baseA = (uint32_t)((warpM * 64 + xrow) * LDS_PADH + xcol);
    const uint32_t baseB = (uint32_t)(ASIZEH + (warpN * 32 + xrow) * LDS_PADH + xcol);

    float acc[4][4][4];
#pragma unroll
    for (int i = 0; i < 4; i++)
#pragma unroll
        for (int j = 0; j < 4; j++)
#pragma unroll
            for (int q = 0; q < 4; q++) acc[i][j][q] = 0.f;

    auto load_stage = [&](int s, int k) {
        const uint32_t dst = sbase + s * STAGEH;
        const char* sA = pA + (size_t)k * 128;
        const char* sB = pB + (size_t)k * 128;
#pragma unroll
        for (int i = 0; i < 4; i++) {
            cp16(dst + offA + i * 16, sA + i * 16);
            cp16(dst + offB + i * 16, sB + i * 16);
        }
    };

    // fragment double buffers
    uint32_t a[2][4][4];
    uint32_t b[2][4][2];

    auto load_frags = [&](int buf, uint32_t st, int kk) {
#pragma unroll
        for (int i = 0; i < 4; i++)
            ldsm_x4(a[buf][i][0], a[buf][i][1], a[buf][i][2], a[buf][i][3],
                    st + baseA + i * (16 * LDS_PADH) + kk * 32);
#pragma unroll
        for (int j2 = 0; j2 < 2; j2++) {
            uint32_t q0, q1, q2, q3;
            ldsm_x4(q0, q1, q2, q3,
                    st + baseB + j2 * (16 * LDS_PADH) + kk * 32);
            b[buf][2 * j2][0] = q0; b[buf][2 * j2 + 1][0] = q1;
            b[buf][2 * j2][1] = q2; b[buf][2 * j2 + 1][1] = q3;
        }
    };

    // prologue: fill stages 0..2 (groups 0..2)
#pragma unroll
    for (int k = 0; k < 3; k++) { load_stage(k, k); cp_commit(); }
    cp_wait2();          // per-thread: groups 0,1 done (stages for chunks 0 and 1)
    __syncthreads();     // cross-thread visibility of those stages
    load_frags(0, sbase, 0);   // chunk 0, kk=0 into buffer 0

    for (int c = 0; c < 64; c++) {
        // Invariants at top of chunk c:
        //  - previous iteration's cp_wait2 (groups <= c) + this barrier make
        //    stage c%4 visible to ALL threads; this iteration's cp_wait2
        //    (groups <= c+1) + barrier make stage (c+1)%4 visible, which the
        //    kk=3 tail prefetch reads.
        //  - all reads of stage (c+3)%4 ended during chunk c-1, so writing it
        //    after this barrier is safe.
        cp_wait2();
        __syncthreads();

        const int kn = c + 3;
        if (kn < 64) load_stage(kn & 3, kn);
        cp_commit();

        const uint32_t stC  = sbase + (c & 3) * STAGEH;
        const uint32_t stC1 = sbase + ((c + 1) & 3) * STAGEH;

#pragma unroll
        for (int kk = 0; kk < 4; kk++) {
            const int cur = kk & 1;
            const int nxt = cur ^ 1;
            // prefetch next fragments while current MMAs issue
            if (kk < 3)            load_frags(nxt, stC, kk + 1);
            else if (c < 63)       load_frags(nxt, stC1, 0);
#pragma unroll
            for (int i = 0; i < 4; i++)
#pragma unroll
                for (int j = 0; j < 4; j++)
                    mma_bf16(acc[i][j], a[cur][i][0], a[cur][i][1],
                             a[cur][i][2], a[cur][i][3],
                             b[cur][j][0], b[cur][j][1]);
        }
    }

    // epilogue: scale by per-row alpha*gamma/127 and store fp32
    const int rq = lane >> 2;
    const int cq = (lane & 3) * 2;
    const int nw = n0 + warpN * 32 + cq;
#pragma unroll
    for (int i = 0; i < 4; i++) {
        const int row = m0 + warpM * 64 + i * 16 + rq;
        const float s0 = g_scales[row];
        const float s1 = g_scales[row + 8];
        float* o0 = out + (size_t)row * 4096 + nw;
        float* o1 = o0 + (size_t)8 * 4096;
#pragma unroll
        for (int j = 0; j < 4; j++) {
            float2 v0; v0.x = acc[i][j][0] * s0; v0.y = acc[i][j][1] * s0;
            *reinterpret_cast<float2*>(o0 + j * 8) = v0;
            float2 v1; v1.x = acc[i][j][2] * s1; v1.y = acc[i][j][3] * s1;
            *reinterpret_cast<float2*>(o1 + j * 8) = v1;
        }
    }
}

// ---------------- launch -----------------------------------------------------
extern "C" void kernel_launch(void* const* d_in, const int* in_sizes, int n_in,
                              void* d_out, int out_size) {
    (void)in_sizes; (void)n_in; (void)out_size;
    const float* x  = reinterpret_cast<const float*>(d_in[0]);
    const float* w  = reinterpret_cast<const float*>(d_in[1]);
    const float* nw = reinterpret_cast<const float*>(d_in[2]);
    float* y = reinterpret_cast<float*>(d_out);

    static bool attr_set = false;
    if (!attr_set) {
        cudaFuncSetAttribute(k_gemm_bf16, cudaFuncAttributeMaxDynamicSharedMemorySize, SMEMH);
        attr_set = true;
    }

    k_abs_partial<<<256, 256>>>(reinterpret_cast<const float4*>(w));
    k_quant_w<<<16384, 256>>>(reinterpret_cast<const float4*>(w));
    k_quant_x<<<4096, 256>>>(x, nw);
    k_gemm_bf16<<<dim3(32, 32), 256, SMEMH>>>(y);
}